// round 14
// baseline (speedup 1.0000x reference)
#include <cuda_runtime.h>
#include <cuda_bf16.h>
#include <cstdint>

#define BB 64
#define TT 2048
#define MM 512
#define PP 512

// Device scratch
__device__ float g_part[8 * BB * MM];            // dsproj k-slab partials (8 slabs)
__device__ __nv_bfloat16 g_UT[MM * MM];          // U_d^T [n][k], bf16
__device__ float g_l[BB * TT];
__device__ int g_done;                           // prep-completion counter (reset each launch)

__device__ __forceinline__ float tanh_fast(float x) {
    float y;
    asm("tanh.approx.f32 %0, %1;" : "=f"(y) : "f"(x));
    return y;
}
__device__ __forceinline__ void cp_async16(uint32_t dst, const void* src) {
    asm volatile("cp.async.cg.shared.global [%0], [%1], 16;" :: "r"(dst), "l"(src) : "memory");
}
__device__ __forceinline__ void cp_commit() {
    asm volatile("cp.async.commit_group;" ::: "memory");
}
__device__ __forceinline__ void cp_wait1() {
    asm volatile("cp.async.wait_group 1;" ::: "memory");
}
__device__ __forceinline__ int ld_acquire_gpu(const int* p) {
    int v;
    asm volatile("ld.acquire.gpu.global.b32 %0, [%1];" : "=r"(v) : "l"(p) : "memory");
    return v;
}

#define SWZ16(r, c) (((r) << 10) + (((c) ^ ((r) & 7)) << 4))

#define A_OFF    0
#define B_OFF    131072
#define DSP_OFF  196608
#define V_OFF    198656
#define PART_OFF 200704
#define SMEM_TOTAL 201280
#define NPREP    128

// ---------------------------------------------------------------------------
// k_main: fused prep (bids 0-127) + GEMM + tanh + v-dot, single kernel.
// Prep slice per prep-CTA: dsproj partials (bgrp=bid>>3, kslab=bid&7, slab=128)
// + 2 transU 32x32 tiles. Flag g_done gates prep-dependent phase; the A-tile
// DRAM load overlaps other CTAs' prep. Wave-2+ CTAs (flag already set) take
// the original issue order (B chunk-0 first).
// ---------------------------------------------------------------------------
__global__ __launch_bounds__(256, 1) void k_main(const float* __restrict__ enc,
                                                 const float* __restrict__ vd,
                                                 const float* __restrict__ bwd,
                                                 const float* __restrict__ bud,
                                                 const float* __restrict__ h,
                                                 const float* __restrict__ cst,
                                                 const float* __restrict__ W,
                                                 const float* __restrict__ U) {
    extern __shared__ char sm[];
    __shared__ int s_ready;
    uint32_t sbase = (uint32_t)__cvta_generic_to_shared(sm);
    uint32_t sA = sbase + A_OFF;
    uint32_t sB = sbase + B_OFF;
    float* dsp_s = (float*)(sm + DSP_OFF);
    float* v_s = (float*)(sm + V_OFF);
    float* part = (float*)(sm + PART_OFF);

    int blk = blockIdx.x;
    int b = blk >> 4;
    int t0 = (blk & 15) << 7;
    int tid = threadIdx.x;
    int lane = tid & 31;
    int wid = tid >> 5;
    int wm = wid & 3;
    int wn = wid >> 2;
    int g = lane >> 2;
    int tig = lane & 3;

    // ---- Sample prep flag (acquire). Wave-2+ CTAs see it set. ----
    if (tid == 0) s_ready = (ld_acquire_gpu(&g_done) >= NPREP);
    __syncthreads();
    int ready = s_ready;

    const __nv_bfloat16* UT = &g_UT[0];

    auto loadBhalf = [&](int nc, int hh) {
        const __nv_bfloat16* srcB = UT + (nc << 6) * MM;
        int cadd = hh << 5;
#pragma unroll
        for (int i = tid; i < 2048; i += 256) {
            int r = i >> 5;
            int c = (i & 31) + cadd;
            cp_async16(sB + SWZ16(r, c), srcB + (r << 9) + (c << 3));
        }
    };

    // Fast path (flag already set): original issue order — B chunk 0 first.
    if (ready) {
        loadBhalf(0, 0); cp_commit();
        loadBhalf(0, 1); cp_commit();
    }

    // ---- Prep slice (bids 0..127): dsproj partials + 2 transU tiles ----
    if (blk < NPREP) {
        // dsproj: bgrp = blk>>3 (4 batches), kslab = blk&7 (128 k)
        float* dsb = (float*)sm;                  // [4][128] = 2KB (A region, pre-A-load)
        int bgrp = blk >> 3;
        int ks = blk & 7;
        for (int i = tid; i < 512; i += 256) {
            int j = i >> 7, kk = i & 127;
            int k = ks * 128 + kk;
            dsb[i] = (k < PP) ? h[(bgrp * 4 + j) * PP + k]
                              : cst[(bgrp * 4 + j) * PP + (k - PP)];
        }
        __syncthreads();
        float a0 = 0.f, a1 = 0.f, a2 = 0.f, a3 = 0.f;
        float b0 = 0.f, b1 = 0.f, b2 = 0.f, b3 = 0.f;
        const float* Wp = W + (ks * 128) * MM + tid;
#pragma unroll 8
        for (int kk = 0; kk < 128; kk++) {
            float w0 = Wp[kk * MM];
            float w1 = Wp[kk * MM + 256];
            float d0 = dsb[kk], d1 = dsb[128 + kk], d2 = dsb[256 + kk], d3 = dsb[384 + kk];
            a0 = fmaf(w0, d0, a0); a1 = fmaf(w0, d1, a1);
            a2 = fmaf(w0, d2, a2); a3 = fmaf(w0, d3, a3);
            b0 = fmaf(w1, d0, b0); b1 = fmaf(w1, d1, b1);
            b2 = fmaf(w1, d2, b2); b3 = fmaf(w1, d3, b3);
        }
        int base = (ks * BB + bgrp * 4) * MM + tid;
        g_part[base] = a0;            g_part[base + 256] = b0;
        g_part[base + MM] = a1;       g_part[base + MM + 256] = b1;
        g_part[base + 2 * MM] = a2;   g_part[base + 2 * MM + 256] = b2;
        g_part[base + 3 * MM] = a3;   g_part[base + 3 * MM + 256] = b3;

        // transU: 2 tiles of 32x32 (256 tiles total over 128 CTAs)
        float* tb = (float*)(sm + 2048);          // 32x33 floats = 4.2KB
        int tx = tid & 31, ty = tid >> 5;
#pragma unroll
        for (int t = 0; t < 2; t++) {
            int m = blk * 2 + t;
            int n0 = (m & 15) << 5;
            int k0 = (m >> 4) << 5;
            __syncthreads();
#pragma unroll
            for (int i = ty; i < 32; i += 8)
                tb[i * 33 + tx] = U[(k0 + i) * MM + n0 + tx];
            __syncthreads();
#pragma unroll
            for (int i = ty; i < 32; i += 8)
                g_UT[(n0 + i) * MM + (k0 + tx)] = __float2bfloat16(tb[tx * 33 + i]);
        }
        __syncthreads();
        if (tid == 0) {
            __threadfence();                       // release g_part/g_UT writes
            atomicAdd(&g_done, 1);
        }
        __syncthreads();                           // dsb/tb reads done before A overwrites
    }

    // ---- A tile load (prep-independent) + v ----
    {
        const float4* src = (const float4*)(enc + (size_t)(b * TT + t0) * MM);
#pragma unroll 8
        for (int i = tid; i < 8192; i += 256) {
            int r = i >> 6;
            int c = i & 63;
            float4 f0 = src[(r << 7) + (c << 1)];
            float4 f1 = src[(r << 7) + (c << 1) + 1];
            __nv_bfloat162 p0 = __floats2bfloat162_rn(f0.x, f0.y);
            __nv_bfloat162 p1 = __floats2bfloat162_rn(f0.z, f0.w);
            __nv_bfloat162 p2 = __floats2bfloat162_rn(f1.x, f1.y);
            __nv_bfloat162 p3 = __floats2bfloat162_rn(f1.z, f1.w);
            uint4 u;
            u.x = *(uint32_t*)&p0; u.y = *(uint32_t*)&p1;
            u.z = *(uint32_t*)&p2; u.w = *(uint32_t*)&p3;
            *(uint4*)(sm + A_OFF + SWZ16(r, c)) = u;
        }
        for (int i = tid; i < MM; i += 256)
            v_s[i] = vd[i];
    }

    // ---- Wait for all prep slices (no-op if ready) ----
    if (tid == 0 && !ready) {
        while (ld_acquire_gpu(&g_done) < NPREP) { __nanosleep(64); }
    }
    __syncthreads();

    // Slow path: B chunk 0 issued after the flag (wave-1 CTAs only)
    if (!ready) {
        loadBhalf(0, 0); cp_commit();
        loadBhalf(0, 1); cp_commit();
    }

    // ---- dsp reduce (8 slabs + biases) ----
    for (int i = tid; i < MM; i += 256) {
        float s = bwd[i] + bud[i];
#pragma unroll
        for (int ks = 0; ks < 8; ks++)
            s += g_part[(ks * BB + b) * MM + i];
        dsp_s[i] = s;
    }

    float lp[4] = {0.f, 0.f, 0.f, 0.f};

    int aRow0 = (wm << 5) + (lane & 15);
    int aRow1 = aRow0 + 16;
    int aCadd = (lane >> 4);
    int bQuad = lane >> 3;
    int bRowIn = lane & 7;
    int bCadd = bQuad & 1;
    int bBlkHalf = bQuad >> 1;
    int bN0 = (wn << 5) + (bBlkHalf << 3) + bRowIn;
    int bN1 = bN0 + 16;

    uint32_t af[2][2][4];
    uint32_t bfr[2][2][4];

    auto loadFrags = [&](int buf, int ks) {
#pragma unroll
        for (int mi = 0; mi < 2; mi++) {
            int r = mi ? aRow1 : aRow0;
            uint32_t addr = sA + SWZ16(r, (ks << 1) + aCadd);
            asm volatile("ldmatrix.sync.aligned.m8n8.x4.shared.b16 {%0,%1,%2,%3}, [%4];"
                         : "=r"(af[buf][mi][0]), "=r"(af[buf][mi][1]),
                           "=r"(af[buf][mi][2]), "=r"(af[buf][mi][3]) : "r"(addr));
        }
#pragma unroll
        for (int jp = 0; jp < 2; jp++) {
            int n = jp ? bN1 : bN0;
            uint32_t addr = sB + SWZ16(n, (ks << 1) + bCadd);
            asm volatile("ldmatrix.sync.aligned.m8n8.x4.shared.b16 {%0,%1,%2,%3}, [%4];"
                         : "=r"(bfr[buf][jp][0]), "=r"(bfr[buf][jp][1]),
                           "=r"(bfr[buf][jp][2]), "=r"(bfr[buf][jp][3]) : "r"(addr));
        }
    };

    float acc[2][4][4];

    for (int nc = 0; nc < 8; nc++) {
#pragma unroll
        for (int mi = 0; mi < 2; mi++)
#pragma unroll
            for (int j = 0; j < 4; j++)
#pragma unroll
                for (int q = 0; q < 4; q++) acc[mi][j][q] = 0.f;

#pragma unroll
        for (int h2 = 0; h2 < 2; h2++) {
            cp_wait1();
            __syncthreads();
            int kbase = h2 << 4;

            loadFrags(0, kbase);
#pragma unroll
            for (int kk = 0; kk < 16; kk++) {
                int cur = kk & 1;
                if (kk < 15) loadFrags(cur ^ 1, kbase + kk + 1);
#pragma unroll
                for (int mi = 0; mi < 2; mi++)
#pragma unroll
                    for (int jp = 0; jp < 2; jp++) {
                        asm volatile("mma.sync.aligned.m16n8k16.row.col.f32.bf16.bf16.f32 "
                            "{%0,%1,%2,%3}, {%4,%5,%6,%7}, {%8,%9}, {%0,%1,%2,%3};"
                            : "+f"(acc[mi][jp * 2][0]), "+f"(acc[mi][jp * 2][1]),
                              "+f"(acc[mi][jp * 2][2]), "+f"(acc[mi][jp * 2][3])
                            : "r"(af[cur][mi][0]), "r"(af[cur][mi][1]),
                              "r"(af[cur][mi][2]), "r"(af[cur][mi][3]),
                              "r"(bfr[cur][jp][0]), "r"(bfr[cur][jp][1]));
                        asm volatile("mma.sync.aligned.m16n8k16.row.col.f32.bf16.bf16.f32 "
                            "{%0,%1,%2,%3}, {%4,%5,%6,%7}, {%8,%9}, {%0,%1,%2,%3};"
                            : "+f"(acc[mi][jp * 2 + 1][0]), "+f"(acc[mi][jp * 2 + 1][1]),
                              "+f"(acc[mi][jp * 2 + 1][2]), "+f"(acc[mi][jp * 2 + 1][3])
                            : "r"(af[cur][mi][0]), "r"(af[cur][mi][1]),
                              "r"(af[cur][mi][2]), "r"(af[cur][mi][3]),
                              "r"(bfr[cur][jp][2]), "r"(bfr[cur][jp][3]));
                    }
            }
            __syncthreads();
            if (nc < 7) loadBhalf(nc + 1, h2);
            cp_commit();
        }

        int nbase = (nc << 6) + (wn << 5) + (tig << 1);
#pragma unroll
        for (int mi = 0; mi < 2; mi++)
#pragma unroll
            for (int j = 0; j < 4; j++) {
                int cb = nbase + (j << 3);
                float v0 = v_s[cb], v1 = v_s[cb + 1];
                float d0 = dsp_s[cb], d1 = dsp_s[cb + 1];
                lp[mi * 2 + 0] += v0 * tanh_fast(acc[mi][j][0] + d0)
                                + v1 * tanh_fast(acc[mi][j][1] + d1);
                lp[mi * 2 + 1] += v0 * tanh_fast(acc[mi][j][2] + d0)
                                + v1 * tanh_fast(acc[mi][j][3] + d1);
            }
    }

#pragma unroll
    for (int q = 0; q < 4; q++) {
        lp[q] += __shfl_xor_sync(0xffffffffu, lp[q], 1);
        lp[q] += __shfl_xor_sync(0xffffffffu, lp[q], 2);
    }
    int row[4];
    row[0] = (wm << 5) + g;
    row[1] = (wm << 5) + 8 + g;
    row[2] = (wm << 5) + 16 + g;
    row[3] = (wm << 5) + 24 + g;
    if (wn == 1 && tig == 0) {
#pragma unroll
        for (int q = 0; q < 4; q++) part[row[q]] = lp[q];
    }
    __syncthreads();
    if (wn == 0 && tig == 0) {
#pragma unroll
        for (int q = 0; q < 4; q++)
            g_l[b * TT + t0 + row[q]] = lp[q] + part[row[q]];
    }
}

// ---------------------------------------------------------------------------
// k_softmax: softmax over T per batch; also resets g_done for the next launch.
// ---------------------------------------------------------------------------
__global__ __launch_bounds__(1024) void k_softmax(float* __restrict__ out) {
    __shared__ float redm[32];
    __shared__ float reds[32];
    if (blockIdx.x == 0 && threadIdx.x == 0) g_done = 0;   // per-launch reset
    int b = blockIdx.x, tid = threadIdx.x, lane = tid & 31, wid = tid >> 5;
    float v0 = g_l[b * TT + tid];
    float v1 = g_l[b * TT + 1024 + tid];
    float m = fmaxf(v0, v1);
#pragma unroll
    for (int o = 16; o; o >>= 1) m = fmaxf(m, __shfl_xor_sync(0xffffffffu, m, o));
    if (lane == 0) redm[wid] = m;
    __syncthreads();
    if (wid == 0) {
        float mm = redm[lane];
#pragma unroll
        for (int o = 16; o; o >>= 1) mm = fmaxf(mm, __shfl_xor_sync(0xffffffffu, mm, o));
        if (lane == 0) redm[0] = mm;
    }
    __syncthreads();
    m = redm[0];
    float e0 = __expf(v0 - m);
    float e1 = __expf(v1 - m);
    float s = e0 + e1;
#pragma unroll
    for (int o = 16; o; o >>= 1) s += __shfl_xor_sync(0xffffffffu, s, o);
    if (lane == 0) reds[wid] = s;
    __syncthreads();
    if (wid == 0) {
        float ss = reds[lane];
#pragma unroll
        for (int o = 16; o; o >>= 1) ss += __shfl_xor_sync(0xffffffffu, ss, o);
        if (lane == 0) reds[0] = ss;
    }
    __syncthreads();
    float inv = 1.0f / reds[0];
    out[b * TT + tid] = e0 * inv;
    out[b * TT + 1024 + tid] = e1 * inv;
}

// ---------------------------------------------------------------------------
extern "C" void kernel_launch(void* const* d_in, const int* in_sizes, int n_in,
                              void* d_out, int out_size) {
    const float* h   = (const float*)d_in[0];
    const float* c   = (const float*)d_in[1];
    const float* enc = (const float*)d_in[2];
    const float* W   = (const float*)d_in[3];
    const float* bwd = (const float*)d_in[4];
    const float* U   = (const float*)d_in[5];
    const float* bud = (const float*)d_in[6];
    const float* vd  = (const float*)d_in[7];
    float* out = (float*)d_out;

    cudaFuncSetAttribute(k_main, cudaFuncAttributeMaxDynamicSharedMemorySize, SMEM_TOTAL);

    k_main<<<(BB * TT) / 128, 256, SMEM_TOTAL>>>(enc, vd, bwd, bud, h, c, W, U);
    k_softmax<<<BB, 1024>>>(out);
}

// round 15
// speedup vs baseline: 1.1342x; 1.1342x over previous
#include <cuda_runtime.h>
#include <cuda_bf16.h>
#include <cstdint>

#define BB 64
#define TT 2048
#define MM 512
#define PP 512

// Device scratch
__device__ float g_part[16 * BB * MM];           // dsproj k-slab partials (16 slabs)
__device__ __nv_bfloat16 g_UT[MM * MM];          // U_d^T [n][k], bf16
__device__ float g_l[BB * TT];

__device__ __forceinline__ float tanh_fast(float x) {
    float y;
    asm("tanh.approx.f32 %0, %1;" : "=f"(y) : "f"(x));
    return y;
}
__device__ __forceinline__ void cp_async16(uint32_t dst, const void* src) {
    asm volatile("cp.async.cg.shared.global [%0], [%1], 16;" :: "r"(dst), "l"(src) : "memory");
}
__device__ __forceinline__ void cp_commit() {
    asm volatile("cp.async.commit_group;" ::: "memory");
}
__device__ __forceinline__ void cp_wait1() {
    asm volatile("cp.async.wait_group 1;" ::: "memory");
}

#define SWZ16(r, c) (((r) << 10) + (((c) ^ ((r) & 7)) << 4))

// ---------------------------------------------------------------------------
// Kernel 1 (fused prep): blocks 0-255 dsproj partials (16 bgrp x 16 kslab,
// slab = 64 k), blocks 256-319 transpose U (64x64 tiles). 512 threads.
// ---------------------------------------------------------------------------
__global__ __launch_bounds__(512) void k_prep(const float* __restrict__ h,
                                              const float* __restrict__ c,
                                              const float* __restrict__ W,
                                              const float* __restrict__ U) {
    __shared__ float buf[64 * 65];
    int blk = blockIdx.x;
    int tid = threadIdx.x;

    if (blk < 256) {
        // ---- dsproj partials: bgrp = blk>>4 (4 batches), kslab = blk&15 ----
        float (*ds)[64] = (float (*)[64])buf;     // [4][64]
        int bgrp = blk >> 4;
        int ks = blk & 15;
        if (tid < 256) {
            int j = tid >> 6, kk = tid & 63;
            int k = ks * 64 + kk;
            ds[j][kk] = (k < PP) ? h[(bgrp * 4 + j) * PP + k]
                                 : c[(bgrp * 4 + j) * PP + (k - PP)];
        }
        __syncthreads();
        float a0 = 0.f, a1 = 0.f, a2 = 0.f, a3 = 0.f;
        const float* Wp = W + (ks * 64) * MM + tid;
#pragma unroll 16
        for (int kk = 0; kk < 64; kk++) {
            float w = Wp[kk * MM];
            a0 = fmaf(w, ds[0][kk], a0);
            a1 = fmaf(w, ds[1][kk], a1);
            a2 = fmaf(w, ds[2][kk], a2);
            a3 = fmaf(w, ds[3][kk], a3);
        }
        int base = (ks * BB + bgrp * 4) * MM + tid;
        g_part[base] = a0;
        g_part[base + MM] = a1;
        g_part[base + 2 * MM] = a2;
        g_part[base + 3 * MM] = a3;
    } else {
        // ---- transU: 64x64 tile; m = blk-256 ----
        int m = blk - 256;
        int n0 = (m & 7) << 6;
        int k0 = (m >> 3) << 6;
        int tx = tid & 63, ty = tid >> 6;
#pragma unroll
        for (int i = ty; i < 64; i += 8)
            buf[i * 65 + tx] = U[(k0 + i) * MM + n0 + tx];
        __syncthreads();
#pragma unroll
        for (int i = ty; i < 64; i += 8)
            g_UT[(n0 + i) * MM + (k0 + tx)] = __float2bfloat16(buf[tx * 65 + i]);
    }
}

// ---------------------------------------------------------------------------
// Kernel 2 (k_main, HMMA-ceiling mainloop): fused GEMM + tanh + v-dot.
// dsproj reduction (16 partials) + biases folded into the prologue.
// ---------------------------------------------------------------------------
#define A_OFF    0
#define B_OFF    131072
#define DSP_OFF  196608
#define V_OFF    198656
#define PART_OFF 200704
#define SMEM_TOTAL 201280

__global__ __launch_bounds__(256, 1) void k_main(const float* __restrict__ enc,
                                                 const float* __restrict__ vd,
                                                 const float* __restrict__ bwd,
                                                 const float* __restrict__ bud) {
    extern __shared__ char sm[];
    uint32_t sbase = (uint32_t)__cvta_generic_to_shared(sm);
    uint32_t sA = sbase + A_OFF;
    uint32_t sB = sbase + B_OFF;
    float* dsp_s = (float*)(sm + DSP_OFF);
    float* v_s = (float*)(sm + V_OFF);
    float* part = (float*)(sm + PART_OFF);

    int blk = blockIdx.x;
    int b = blk >> 4;
    int t0 = (blk & 15) << 7;
    int tid = threadIdx.x;
    int lane = tid & 31;
    int wid = tid >> 5;
    int wm = wid & 3;
    int wn = wid >> 2;
    int g = lane >> 2;
    int tig = lane & 3;

    const __nv_bfloat16* UT = &g_UT[0];

    auto loadBhalf = [&](int nc, int hh) {
        const __nv_bfloat16* srcB = UT + (nc << 6) * MM;
        int cadd = hh << 5;
#pragma unroll
        for (int i = tid; i < 2048; i += 256) {
            int r = i >> 5;
            int c = (i & 31) + cadd;
            cp_async16(sB + SWZ16(r, c), srcB + (r << 9) + (c << 3));
        }
    };

    loadBhalf(0, 0); cp_commit();
    loadBhalf(0, 1); cp_commit();

    // Load A tile + fold dsproj reduce (16 partials + biases) + v
    {
        const float4* src = (const float4*)(enc + (size_t)(b * TT + t0) * MM);
#pragma unroll 8
        for (int i = tid; i < 8192; i += 256) {
            int r = i >> 6;
            int c = i & 63;
            float4 f0 = src[(r << 7) + (c << 1)];
            float4 f1 = src[(r << 7) + (c << 1) + 1];
            __nv_bfloat162 p0 = __floats2bfloat162_rn(f0.x, f0.y);
            __nv_bfloat162 p1 = __floats2bfloat162_rn(f0.z, f0.w);
            __nv_bfloat162 p2 = __floats2bfloat162_rn(f1.x, f1.y);
            __nv_bfloat162 p3 = __floats2bfloat162_rn(f1.z, f1.w);
            uint4 u;
            u.x = *(uint32_t*)&p0; u.y = *(uint32_t*)&p1;
            u.z = *(uint32_t*)&p2; u.w = *(uint32_t*)&p3;
            *(uint4*)(sm + A_OFF + SWZ16(r, c)) = u;
        }
        for (int i = tid; i < MM; i += 256) {
            float s = bwd[i] + bud[i];
#pragma unroll
            for (int ks = 0; ks < 16; ks++)
                s += g_part[(ks * BB + b) * MM + i];
            dsp_s[i] = s;
            v_s[i] = vd[i];
        }
    }

    float lp[4] = {0.f, 0.f, 0.f, 0.f};

    int aRow0 = (wm << 5) + (lane & 15);
    int aRow1 = aRow0 + 16;
    int aCadd = (lane >> 4);
    int bQuad = lane >> 3;
    int bRowIn = lane & 7;
    int bCadd = bQuad & 1;
    int bBlkHalf = bQuad >> 1;
    int bN0 = (wn << 5) + (bBlkHalf << 3) + bRowIn;
    int bN1 = bN0 + 16;

    uint32_t af[2][2][4];
    uint32_t bfr[2][2][4];

    auto loadFrags = [&](int buf, int ks) {
#pragma unroll
        for (int mi = 0; mi < 2; mi++) {
            int r = mi ? aRow1 : aRow0;
            uint32_t addr = sA + SWZ16(r, (ks << 1) + aCadd);
            asm volatile("ldmatrix.sync.aligned.m8n8.x4.shared.b16 {%0,%1,%2,%3}, [%4];"
                         : "=r"(af[buf][mi][0]), "=r"(af[buf][mi][1]),
                           "=r"(af[buf][mi][2]), "=r"(af[buf][mi][3]) : "r"(addr));
        }
#pragma unroll
        for (int jp = 0; jp < 2; jp++) {
            int n = jp ? bN1 : bN0;
            uint32_t addr = sB + SWZ16(n, (ks << 1) + bCadd);
            asm volatile("ldmatrix.sync.aligned.m8n8.x4.shared.b16 {%0,%1,%2,%3}, [%4];"
                         : "=r"(bfr[buf][jp][0]), "=r"(bfr[buf][jp][1]),
                           "=r"(bfr[buf][jp][2]), "=r"(bfr[buf][jp][3]) : "r"(addr));
        }
    };

    float acc[2][4][4];

    for (int nc = 0; nc < 8; nc++) {
#pragma unroll
        for (int mi = 0; mi < 2; mi++)
#pragma unroll
            for (int j = 0; j < 4; j++)
#pragma unroll
                for (int q = 0; q < 4; q++) acc[mi][j][q] = 0.f;

#pragma unroll
        for (int h = 0; h < 2; h++) {
            cp_wait1();
            __syncthreads();
            int kbase = h << 4;

            loadFrags(0, kbase);
#pragma unroll
            for (int kk = 0; kk < 16; kk++) {
                int cur = kk & 1;
                if (kk < 15) loadFrags(cur ^ 1, kbase + kk + 1);
#pragma unroll
                for (int mi = 0; mi < 2; mi++)
#pragma unroll
                    for (int jp = 0; jp < 2; jp++) {
                        asm volatile("mma.sync.aligned.m16n8k16.row.col.f32.bf16.bf16.f32 "
                            "{%0,%1,%2,%3}, {%4,%5,%6,%7}, {%8,%9}, {%0,%1,%2,%3};"
                            : "+f"(acc[mi][jp * 2][0]), "+f"(acc[mi][jp * 2][1]),
                              "+f"(acc[mi][jp * 2][2]), "+f"(acc[mi][jp * 2][3])
                            : "r"(af[cur][mi][0]), "r"(af[cur][mi][1]),
                              "r"(af[cur][mi][2]), "r"(af[cur][mi][3]),
                              "r"(bfr[cur][jp][0]), "r"(bfr[cur][jp][1]));
                        asm volatile("mma.sync.aligned.m16n8k16.row.col.f32.bf16.bf16.f32 "
                            "{%0,%1,%2,%3}, {%4,%5,%6,%7}, {%8,%9}, {%0,%1,%2,%3};"
                            : "+f"(acc[mi][jp * 2 + 1][0]), "+f"(acc[mi][jp * 2 + 1][1]),
                              "+f"(acc[mi][jp * 2 + 1][2]), "+f"(acc[mi][jp * 2 + 1][3])
                            : "r"(af[cur][mi][0]), "r"(af[cur][mi][1]),
                              "r"(af[cur][mi][2]), "r"(af[cur][mi][3]),
                              "r"(bfr[cur][jp][2]), "r"(bfr[cur][jp][3]));
                    }
            }
            __syncthreads();
            if (nc < 7) loadBhalf(nc + 1, h);
            cp_commit();
        }

        int nbase = (nc << 6) + (wn << 5) + (tig << 1);
#pragma unroll
        for (int mi = 0; mi < 2; mi++)
#pragma unroll
            for (int j = 0; j < 4; j++) {
                int cb = nbase + (j << 3);
                float v0 = v_s[cb], v1 = v_s[cb + 1];
                float d0 = dsp_s[cb], d1 = dsp_s[cb + 1];
                lp[mi * 2 + 0] += v0 * tanh_fast(acc[mi][j][0] + d0)
                                + v1 * tanh_fast(acc[mi][j][1] + d1);
                lp[mi * 2 + 1] += v0 * tanh_fast(acc[mi][j][2] + d0)
                                + v1 * tanh_fast(acc[mi][j][3] + d1);
            }
    }

#pragma unroll
    for (int q = 0; q < 4; q++) {
        lp[q] += __shfl_xor_sync(0xffffffffu, lp[q], 1);
        lp[q] += __shfl_xor_sync(0xffffffffu, lp[q], 2);
    }
    int row[4];
    row[0] = (wm << 5) + g;
    row[1] = (wm << 5) + 8 + g;
    row[2] = (wm << 5) + 16 + g;
    row[3] = (wm << 5) + 24 + g;
    if (wn == 1 && tig == 0) {
#pragma unroll
        for (int q = 0; q < 4; q++) part[row[q]] = lp[q];
    }
    __syncthreads();
    if (wn == 0 && tig == 0) {
#pragma unroll
        for (int q = 0; q < 4; q++)
            g_l[b * TT + t0 + row[q]] = lp[q] + part[row[q]];
    }
}

// ---------------------------------------------------------------------------
// Kernel 3: softmax over T per batch. 1024 threads, 2 elements each.
// ---------------------------------------------------------------------------
__global__ __launch_bounds__(1024) void k_softmax(float* __restrict__ out) {
    __shared__ float redm[32];
    __shared__ float reds[32];
    int b = blockIdx.x, tid = threadIdx.x, lane = tid & 31, wid = tid >> 5;
    float v0 = g_l[b * TT + tid];
    float v1 = g_l[b * TT + 1024 + tid];
    float m = fmaxf(v0, v1);
#pragma unroll
    for (int o = 16; o; o >>= 1) m = fmaxf(m, __shfl_xor_sync(0xffffffffu, m, o));
    if (lane == 0) redm[wid] = m;
    __syncthreads();
    if (wid == 0) {
        float mm = redm[lane];
#pragma unroll
        for (int o = 16; o; o >>= 1) mm = fmaxf(mm, __shfl_xor_sync(0xffffffffu, mm, o));
        if (lane == 0) redm[0] = mm;
    }
    __syncthreads();
    m = redm[0];
    float e0 = __expf(v0 - m);
    float e1 = __expf(v1 - m);
    float s = e0 + e1;
#pragma unroll
    for (int o = 16; o; o >>= 1) s += __shfl_xor_sync(0xffffffffu, s, o);
    if (lane == 0) reds[wid] = s;
    __syncthreads();
    if (wid == 0) {
        float ss = reds[lane];
#pragma unroll
        for (int o = 16; o; o >>= 1) ss += __shfl_xor_sync(0xffffffffu, ss, o);
        if (lane == 0) reds[0] = ss;
    }
    __syncthreads();
    float inv = 1.0f / reds[0];
    out[b * TT + tid] = e0 * inv;
    out[b * TT + 1024 + tid] = e1 * inv;
}

// ---------------------------------------------------------------------------
extern "C" void kernel_launch(void* const* d_in, const int* in_sizes, int n_in,
                              void* d_out, int out_size) {
    const float* h   = (const float*)d_in[0];
    const float* c   = (const float*)d_in[1];
    const float* enc = (const float*)d_in[2];
    const float* W   = (const float*)d_in[3];
    const float* bwd = (const float*)d_in[4];
    const float* U   = (const float*)d_in[5];
    const float* bud = (const float*)d_in[6];
    const float* vd  = (const float*)d_in[7];
    float* out = (float*)d_out;

    cudaFuncSetAttribute(k_main, cudaFuncAttributeMaxDynamicSharedMemorySize, SMEM_TOTAL);

    k_prep<<<320, 512>>>(h, c, W, U);
    k_main<<<(BB * TT) / 128, 256, SMEM_TOTAL>>>(enc, vd, bwd, bud);
    k_softmax<<<BB, 1024>>>(out);
}

// round 16
// speedup vs baseline: 1.1513x; 1.0151x over previous
#include <cuda_runtime.h>
#include <cuda_bf16.h>
#include <cstdint>

#define BB 64
#define TT 2048
#define MM 512
#define PP 512

// Device scratch
__device__ float g_part[16 * BB * MM];           // dsproj k-slab partials (16 slabs)
__device__ __nv_bfloat16 g_UT[MM * MM];          // U_d^T [n][k], bf16
__device__ float g_l[BB * TT];

__device__ __forceinline__ float tanh_fast(float x) {
    float y;
    asm("tanh.approx.f32 %0, %1;" : "=f"(y) : "f"(x));
    return y;
}
__device__ __forceinline__ void cp_async16(uint32_t dst, const void* src) {
    asm volatile("cp.async.cg.shared.global [%0], [%1], 16;" :: "r"(dst), "l"(src) : "memory");
}
__device__ __forceinline__ void cp_commit() {
    asm volatile("cp.async.commit_group;" ::: "memory");
}
__device__ __forceinline__ void cp_wait1() {
    asm volatile("cp.async.wait_group 1;" ::: "memory");
}

#define SWZ16(r, c) (((r) << 10) + (((c) ^ ((r) & 7)) << 4))

// ---------------------------------------------------------------------------
// Kernel 1 (fused prep): blocks 0-255 dsproj partials (16 bgrp x 16 kslab,
// slab = 64 k), blocks 256-319 transpose U (64x64 tiles). 512 threads.
// ---------------------------------------------------------------------------
__global__ __launch_bounds__(512) void k_prep(const float* __restrict__ h,
                                              const float* __restrict__ c,
                                              const float* __restrict__ W,
                                              const float* __restrict__ U) {
    __shared__ float buf[64 * 65];
    int blk = blockIdx.x;
    int tid = threadIdx.x;

    if (blk < 256) {
        // ---- dsproj partials: bgrp = blk>>4 (4 batches), kslab = blk&15 ----
        float (*ds)[64] = (float (*)[64])buf;     // [4][64]
        int bgrp = blk >> 4;
        int ks = blk & 15;
        if (tid < 256) {
            int j = tid >> 6, kk = tid & 63;
            int k = ks * 64 + kk;
            ds[j][kk] = (k < PP) ? h[(bgrp * 4 + j) * PP + k]
                                 : c[(bgrp * 4 + j) * PP + (k - PP)];
        }
        __syncthreads();
        float a0 = 0.f, a1 = 0.f, a2 = 0.f, a3 = 0.f;
        const float* Wp = W + (ks * 64) * MM + tid;
#pragma unroll 16
        for (int kk = 0; kk < 64; kk++) {
            float w = Wp[kk * MM];
            a0 = fmaf(w, ds[0][kk], a0);
            a1 = fmaf(w, ds[1][kk], a1);
            a2 = fmaf(w, ds[2][kk], a2);
            a3 = fmaf(w, ds[3][kk], a3);
        }
        int base = (ks * BB + bgrp * 4) * MM + tid;
        g_part[base] = a0;
        g_part[base + MM] = a1;
        g_part[base + 2 * MM] = a2;
        g_part[base + 3 * MM] = a3;
    } else {
        // ---- transU: 64x64 tile; m = blk-256 ----
        int m = blk - 256;
        int n0 = (m & 7) << 6;
        int k0 = (m >> 3) << 6;
        int tx = tid & 63, ty = tid >> 6;
#pragma unroll
        for (int i = ty; i < 64; i += 8)
            buf[i * 65 + tx] = U[(k0 + i) * MM + n0 + tx];
        __syncthreads();
#pragma unroll
        for (int i = ty; i < 64; i += 8)
            g_UT[(n0 + i) * MM + (k0 + tx)] = __float2bfloat16(buf[tx * 65 + i]);
    }
}

// ---------------------------------------------------------------------------
// Kernel 2 (k_main): fused GEMM + tanh + v-dot.
// NEW vs R9: prologue loads only A k-half-0 (cols 0-255); A k-half-1 is
// software-pipelined INTO the nc=0,h=0 MMA phase (16 row-slab pieces,
// depth-4 LDG->STS pipeline) so half the A DRAM time hides under tensor work.
// h=0 phases read only A cols <256; h=1 phases read cols >=256 (barrier-
// separated), so the overlap is race-free.
// ---------------------------------------------------------------------------
#define A_OFF    0
#define B_OFF    131072
#define DSP_OFF  196608
#define V_OFF    198656
#define PART_OFF 200704
#define SMEM_TOTAL 201280

__global__ __launch_bounds__(256, 1) void k_main(const float* __restrict__ enc,
                                                 const float* __restrict__ vd,
                                                 const float* __restrict__ bwd,
                                                 const float* __restrict__ bud) {
    extern __shared__ char sm[];
    uint32_t sbase = (uint32_t)__cvta_generic_to_shared(sm);
    uint32_t sA = sbase + A_OFF;
    uint32_t sB = sbase + B_OFF;
    float* dsp_s = (float*)(sm + DSP_OFF);
    float* v_s = (float*)(sm + V_OFF);
    float* part = (float*)(sm + PART_OFF);

    int blk = blockIdx.x;
    int b = blk >> 4;
    int t0 = (blk & 15) << 7;
    int tid = threadIdx.x;
    int lane = tid & 31;
    int wid = tid >> 5;
    int wm = wid & 3;
    int wn = wid >> 2;
    int g = lane >> 2;
    int tig = lane & 3;

    const __nv_bfloat16* UT = &g_UT[0];
    const float4* srcA = (const float4*)(enc + (size_t)(b * TT + t0) * MM);

    auto loadBhalf = [&](int nc, int hh) {
        const __nv_bfloat16* srcB = UT + (nc << 6) * MM;
        int cadd = hh << 5;
#pragma unroll
        for (int i = tid; i < 2048; i += 256) {
            int r = i >> 5;
            int c = (i & 31) + cadd;
            cp_async16(sB + SWZ16(r, c), srcB + (r << 9) + (c << 3));
        }
    };

    loadBhalf(0, 0); cp_commit();
    loadBhalf(0, 1); cp_commit();

    // ---- Prologue: A k-half-0 only (cols 0-255) + dsp reduce + v ----
    {
#pragma unroll 8
        for (int i = tid; i < 4096; i += 256) {
            int r = i >> 5;
            int c = i & 31;                       // 16B chunks 0..31 (bf16 cols 0..255)
            float4 f0 = srcA[(r << 7) + (c << 1)];
            float4 f1 = srcA[(r << 7) + (c << 1) + 1];
            __nv_bfloat162 p0 = __floats2bfloat162_rn(f0.x, f0.y);
            __nv_bfloat162 p1 = __floats2bfloat162_rn(f0.z, f0.w);
            __nv_bfloat162 p2 = __floats2bfloat162_rn(f1.x, f1.y);
            __nv_bfloat162 p3 = __floats2bfloat162_rn(f1.z, f1.w);
            uint4 u;
            u.x = *(uint32_t*)&p0; u.y = *(uint32_t*)&p1;
            u.z = *(uint32_t*)&p2; u.w = *(uint32_t*)&p3;
            *(uint4*)(sm + A_OFF + SWZ16(r, c)) = u;
        }
        for (int i = tid; i < MM; i += 256) {
            float s = bwd[i] + bud[i];
#pragma unroll
            for (int ks = 0; ks < 16; ks++)
                s += g_part[(ks * BB + b) * MM + i];
            dsp_s[i] = s;
            v_s[i] = vd[i];
        }
    }

    float lp[4] = {0.f, 0.f, 0.f, 0.f};

    int aRow0 = (wm << 5) + (lane & 15);
    int aRow1 = aRow0 + 16;
    int aCadd = (lane >> 4);
    int bQuad = lane >> 3;
    int bRowIn = lane & 7;
    int bCadd = bQuad & 1;
    int bBlkHalf = bQuad >> 1;
    int bN0 = (wn << 5) + (bBlkHalf << 3) + bRowIn;
    int bN1 = bN0 + 16;

    uint32_t af[2][2][4];
    uint32_t bfr[2][2][4];
    float4 pf[4][2];                               // A half-1 pieces in flight

    auto loadFrags = [&](int buf, int ks) {
#pragma unroll
        for (int mi = 0; mi < 2; mi++) {
            int r = mi ? aRow1 : aRow0;
            uint32_t addr = sA + SWZ16(r, (ks << 1) + aCadd);
            asm volatile("ldmatrix.sync.aligned.m8n8.x4.shared.b16 {%0,%1,%2,%3}, [%4];"
                         : "=r"(af[buf][mi][0]), "=r"(af[buf][mi][1]),
                           "=r"(af[buf][mi][2]), "=r"(af[buf][mi][3]) : "r"(addr));
        }
#pragma unroll
        for (int jp = 0; jp < 2; jp++) {
            int n = jp ? bN1 : bN0;
            uint32_t addr = sB + SWZ16(n, (ks << 1) + bCadd);
            asm volatile("ldmatrix.sync.aligned.m8n8.x4.shared.b16 {%0,%1,%2,%3}, [%4];"
                         : "=r"(bfr[buf][jp][0]), "=r"(bfr[buf][jp][1]),
                           "=r"(bfr[buf][jp][2]), "=r"(bfr[buf][jp][3]) : "r"(addr));
        }
    };

    float acc[2][4][4];

    auto mmaStep = [&](int cur) {
#pragma unroll
        for (int mi = 0; mi < 2; mi++)
#pragma unroll
            for (int jp = 0; jp < 2; jp++) {
                asm volatile("mma.sync.aligned.m16n8k16.row.col.f32.bf16.bf16.f32 "
                    "{%0,%1,%2,%3}, {%4,%5,%6,%7}, {%8,%9}, {%0,%1,%2,%3};"
                    : "+f"(acc[mi][jp * 2][0]), "+f"(acc[mi][jp * 2][1]),
                      "+f"(acc[mi][jp * 2][2]), "+f"(acc[mi][jp * 2][3])
                    : "r"(af[cur][mi][0]), "r"(af[cur][mi][1]),
                      "r"(af[cur][mi][2]), "r"(af[cur][mi][3]),
                      "r"(bfr[cur][jp][0]), "r"(bfr[cur][jp][1]));
                asm volatile("mma.sync.aligned.m16n8k16.row.col.f32.bf16.bf16.f32 "
                    "{%0,%1,%2,%3}, {%4,%5,%6,%7}, {%8,%9}, {%0,%1,%2,%3};"
                    : "+f"(acc[mi][jp * 2 + 1][0]), "+f"(acc[mi][jp * 2 + 1][1]),
                      "+f"(acc[mi][jp * 2 + 1][2]), "+f"(acc[mi][jp * 2 + 1][3])
                    : "r"(af[cur][mi][0]), "r"(af[cur][mi][1]),
                      "r"(af[cur][mi][2]), "r"(af[cur][mi][3]),
                      "r"(bfr[cur][jp][2]), "r"(bfr[cur][jp][3]));
            }
    };

    // A half-1 piece p = row slab [p*8, p*8+8), all 32 chunks (cols 256-511)
    auto ldgPiece = [&](int p) {
        int i = (p << 8) + tid;
        int r = i >> 5;
        int cc = (i & 31) + 32;
        pf[p & 3][0] = srcA[(r << 7) + (cc << 1)];
        pf[p & 3][1] = srcA[(r << 7) + (cc << 1) + 1];
    };
    auto stsPiece = [&](int p) {
        float4 f0 = pf[p & 3][0];
        float4 f1 = pf[p & 3][1];
        __nv_bfloat162 p0 = __floats2bfloat162_rn(f0.x, f0.y);
        __nv_bfloat162 p1 = __floats2bfloat162_rn(f0.z, f0.w);
        __nv_bfloat162 p2 = __floats2bfloat162_rn(f1.x, f1.y);
        __nv_bfloat162 p3 = __floats2bfloat162_rn(f1.z, f1.w);
        uint4 u;
        u.x = *(uint32_t*)&p0; u.y = *(uint32_t*)&p1;
        u.z = *(uint32_t*)&p2; u.w = *(uint32_t*)&p3;
        int i = (p << 8) + tid;
        int r = i >> 5;
        int cc = (i & 31) + 32;
        *(uint4*)(sm + A_OFF + SWZ16(r, cc)) = u;
    };

    for (int nc = 0; nc < 8; nc++) {
#pragma unroll
        for (int mi = 0; mi < 2; mi++)
#pragma unroll
            for (int j = 0; j < 4; j++)
#pragma unroll
                for (int q = 0; q < 4; q++) acc[mi][j][q] = 0.f;

#pragma unroll
        for (int h = 0; h < 2; h++) {
            cp_wait1();
            __syncthreads();
            int kbase = h << 4;

            loadFrags(0, kbase);
            if (h == 0 && nc == 0) {
                // Special phase: interleave A half-1 load with MMA (depth-4 pipe)
#pragma unroll
                for (int kk = 0; kk < 16; kk++) {
                    int cur = kk & 1;
                    if (kk < 15) loadFrags(cur ^ 1, kk + 1);
                    if (kk >= 4) stsPiece(kk - 4);
                    ldgPiece(kk);
                    mmaStep(cur);
                }
                stsPiece(12); stsPiece(13); stsPiece(14); stsPiece(15);
            } else {
#pragma unroll
                for (int kk = 0; kk < 16; kk++) {
                    int cur = kk & 1;
                    if (kk < 15) loadFrags(cur ^ 1, kbase + kk + 1);
                    mmaStep(cur);
                }
            }
            __syncthreads();
            if (nc < 7) loadBhalf(nc + 1, h);
            cp_commit();
        }

        int nbase = (nc << 6) + (wn << 5) + (tig << 1);
#pragma unroll
        for (int mi = 0; mi < 2; mi++)
#pragma unroll
            for (int j = 0; j < 4; j++) {
                int cb = nbase + (j << 3);
                float v0 = v_s[cb], v1 = v_s[cb + 1];
                float d0 = dsp_s[cb], d1 = dsp_s[cb + 1];
                lp[mi * 2 + 0] += v0 * tanh_fast(acc[mi][j][0] + d0)
                                + v1 * tanh_fast(acc[mi][j][1] + d1);
                lp[mi * 2 + 1] += v0 * tanh_fast(acc[mi][j][2] + d0)
                                + v1 * tanh_fast(acc[mi][j][3] + d1);
            }
    }

#pragma unroll
    for (int q = 0; q < 4; q++) {
        lp[q] += __shfl_xor_sync(0xffffffffu, lp[q], 1);
        lp[q] += __shfl_xor_sync(0xffffffffu, lp[q], 2);
    }
    int row[4];
    row[0] = (wm << 5) + g;
    row[1] = (wm << 5) + 8 + g;
    row[2] = (wm << 5) + 16 + g;
    row[3] = (wm << 5) + 24 + g;
    if (wn == 1 && tig == 0) {
#pragma unroll
        for (int q = 0; q < 4; q++) part[row[q]] = lp[q];
    }
    __syncthreads();
    if (wn == 0 && tig == 0) {
#pragma unroll
        for (int q = 0; q < 4; q++)
            g_l[b * TT + t0 + row[q]] = lp[q] + part[row[q]];
    }
}

// ---------------------------------------------------------------------------
// Kernel 3: softmax over T per batch. 1024 threads, 2 elements each.
// ---------------------------------------------------------------------------
__global__ __launch_bounds__(1024) void k_softmax(float* __restrict__ out) {
    __shared__ float redm[32];
    __shared__ float reds[32];
    int b = blockIdx.x, tid = threadIdx.x, lane = tid & 31, wid = tid >> 5;
    float v0 = g_l[b * TT + tid];
    float v1 = g_l[b * TT + 1024 + tid];
    float m = fmaxf(v0, v1);
#pragma unroll
    for (int o = 16; o; o >>= 1) m = fmaxf(m, __shfl_xor_sync(0xffffffffu, m, o));
    if (lane == 0) redm[wid] = m;
    __syncthreads();
    if (wid == 0) {
        float mm = redm[lane];
#pragma unroll
        for (int o = 16; o; o >>= 1) mm = fmaxf(mm, __shfl_xor_sync(0xffffffffu, mm, o));
        if (lane == 0) redm[0] = mm;
    }
    __syncthreads();
    m = redm[0];
    float e0 = __expf(v0 - m);
    float e1 = __expf(v1 - m);
    float s = e0 + e1;
#pragma unroll
    for (int o = 16; o; o >>= 1) s += __shfl_xor_sync(0xffffffffu, s, o);
    if (lane == 0) reds[wid] = s;
    __syncthreads();
    if (wid == 0) {
        float ss = reds[lane];
#pragma unroll
        for (int o = 16; o; o >>= 1) ss += __shfl_xor_sync(0xffffffffu, ss, o);
        if (lane == 0) reds[0] = ss;
    }
    __syncthreads();
    float inv = 1.0f / reds[0];
    out[b * TT + tid] = e0 * inv;
    out[b * TT + 1024 + tid] = e1 * inv;
}

// ---------------------------------------------------------------------------
extern "C" void kernel_launch(void* const* d_in, const int* in_sizes, int n_in,
                              void* d_out, int out_size) {
    const float* h   = (const float*)d_in[0];
    const float* c   = (const float*)d_in[1];
    const float* enc = (const float*)d_in[2];
    const float* W   = (const float*)d_in[3];
    const float* bwd = (const float*)d_in[4];
    const float* U   = (const float*)d_in[5];
    const float* bud = (const float*)d_in[6];
    const float* vd  = (const float*)d_in[7];
    float* out = (float*)d_out;

    cudaFuncSetAttribute(k_main, cudaFuncAttributeMaxDynamicSharedMemorySize, SMEM_TOTAL);

    k_prep<<<320, 512>>>(h, c, W, U);
    k_main<<<(BB * TT) / 128, 256, SMEM_TOTAL>>>(enc, vd, bwd, bud);
    k_softmax<<<BB, 1024>>>(out);
}

// round 17
// speedup vs baseline: 1.1524x; 1.0009x over previous
#include <cuda_runtime.h>
#include <cuda_bf16.h>
#include <cstdint>

#define BB 64
#define TT 2048
#define MM 512
#define PP 512

// Device scratch
__device__ float g_part[16 * BB * MM];           // dsproj k-slab partials (16 slabs)
__device__ __nv_bfloat16 g_UT[MM * MM];          // U_d^T [n][k], bf16
__device__ float g_l[BB * TT];

__device__ __forceinline__ float tanh_fast(float x) {
    float y;
    asm("tanh.approx.f32 %0, %1;" : "=f"(y) : "f"(x));
    return y;
}
__device__ __forceinline__ void cp_async16(uint32_t dst, const void* src) {
    asm volatile("cp.async.cg.shared.global [%0], [%1], 16;" :: "r"(dst), "l"(src) : "memory");
}
__device__ __forceinline__ void cp_commit() {
    asm volatile("cp.async.commit_group;" ::: "memory");
}
__device__ __forceinline__ void cp_wait1() {
    asm volatile("cp.async.wait_group 1;" ::: "memory");
}

#define SWZ16(r, c) (((r) << 10) + (((c) ^ ((r) & 7)) << 4))

// ---------------------------------------------------------------------------
// Kernel 1 (fused prep): blocks 0-255 dsproj partials (16 bgrp x 16 kslab,
// slab = 64 k), blocks 256-319 transpose U (64x64 tiles). 512 threads.
// ---------------------------------------------------------------------------
__global__ __launch_bounds__(512) void k_prep(const float* __restrict__ h,
                                              const float* __restrict__ c,
                                              const float* __restrict__ W,
                                              const float* __restrict__ U) {
    __shared__ float buf[64 * 65];
    int blk = blockIdx.x;
    int tid = threadIdx.x;

    if (blk < 256) {
        // ---- dsproj partials: bgrp = blk>>4 (4 batches), kslab = blk&15 ----
        float (*ds)[64] = (float (*)[64])buf;     // [4][64]
        int bgrp = blk >> 4;
        int ks = blk & 15;
        if (tid < 256) {
            int j = tid >> 6, kk = tid & 63;
            int k = ks * 64 + kk;
            ds[j][kk] = (k < PP) ? h[(bgrp * 4 + j) * PP + k]
                                 : c[(bgrp * 4 + j) * PP + (k - PP)];
        }
        __syncthreads();
        float a0 = 0.f, a1 = 0.f, a2 = 0.f, a3 = 0.f;
        const float* Wp = W + (ks * 64) * MM + tid;
#pragma unroll 16
        for (int kk = 0; kk < 64; kk++) {
            float w = Wp[kk * MM];
            a0 = fmaf(w, ds[0][kk], a0);
            a1 = fmaf(w, ds[1][kk], a1);
            a2 = fmaf(w, ds[2][kk], a2);
            a3 = fmaf(w, ds[3][kk], a3);
        }
        int base = (ks * BB + bgrp * 4) * MM + tid;
        g_part[base] = a0;
        g_part[base + MM] = a1;
        g_part[base + 2 * MM] = a2;
        g_part[base + 3 * MM] = a3;
    } else {
        // ---- transU: 64x64 tile; m = blk-256 ----
        int m = blk - 256;
        int n0 = (m & 7) << 6;
        int k0 = (m >> 3) << 6;
        int tx = tid & 63, ty = tid >> 6;
#pragma unroll
        for (int i = ty; i < 64; i += 8)
            buf[i * 65 + tx] = U[(k0 + i) * MM + n0 + tx];
        __syncthreads();
#pragma unroll
        for (int i = ty; i < 64; i += 8)
            g_UT[(n0 + i) * MM + (k0 + tx)] = __float2bfloat16(buf[tx * 65 + i]);
    }
}

// ---------------------------------------------------------------------------
// Kernel 2 (k_main): fused GEMM + tanh + v-dot.
// Prologue loads A k-half-0 (cols 0-255) + PREFETCHES pieces 0-3 of half-1.
// A k-half-1 streams through the nc=0,h=0 MMA phase with a strict depth-4
// LDG->STS pipeline (stsPiece(kk); ldgPiece(kk+4)) — no post-loop tail.
// h=0 phases read only A cols <256; h=1 phases read cols >=256.
// ---------------------------------------------------------------------------
#define A_OFF    0
#define B_OFF    131072
#define DSP_OFF  196608
#define V_OFF    198656
#define PART_OFF 200704
#define SMEM_TOTAL 201280

__global__ __launch_bounds__(256, 1) void k_main(const float* __restrict__ enc,
                                                 const float* __restrict__ vd,
                                                 const float* __restrict__ bwd,
                                                 const float* __restrict__ bud) {
    extern __shared__ char sm[];
    uint32_t sbase = (uint32_t)__cvta_generic_to_shared(sm);
    uint32_t sA = sbase + A_OFF;
    uint32_t sB = sbase + B_OFF;
    float* dsp_s = (float*)(sm + DSP_OFF);
    float* v_s = (float*)(sm + V_OFF);
    float* part = (float*)(sm + PART_OFF);

    int blk = blockIdx.x;
    int b = blk >> 4;
    int t0 = (blk & 15) << 7;
    int tid = threadIdx.x;
    int lane = tid & 31;
    int wid = tid >> 5;
    int wm = wid & 3;
    int wn = wid >> 2;
    int g = lane >> 2;
    int tig = lane & 3;

    const __nv_bfloat16* UT = &g_UT[0];
    const float4* srcA = (const float4*)(enc + (size_t)(b * TT + t0) * MM);

    auto loadBhalf = [&](int nc, int hh) {
        const __nv_bfloat16* srcB = UT + (nc << 6) * MM;
        int cadd = hh << 5;
#pragma unroll
        for (int i = tid; i < 2048; i += 256) {
            int r = i >> 5;
            int c = (i & 31) + cadd;
            cp_async16(sB + SWZ16(r, c), srcB + (r << 9) + (c << 3));
        }
    };

    loadBhalf(0, 0); cp_commit();
    loadBhalf(0, 1); cp_commit();

    float4 pf[4][2];                               // A half-1 pieces in flight

    // A half-1 piece p = row slab [p*8, p*8+8), chunks 32-63 (cols 256-511)
    auto ldgPiece = [&](int p) {
        int i = (p << 8) + tid;
        int r = i >> 5;
        int cc = (i & 31) + 32;
        pf[p & 3][0] = srcA[(r << 7) + (cc << 1)];
        pf[p & 3][1] = srcA[(r << 7) + (cc << 1) + 1];
    };
    auto stsPiece = [&](int p) {
        float4 f0 = pf[p & 3][0];
        float4 f1 = pf[p & 3][1];
        __nv_bfloat162 p0 = __floats2bfloat162_rn(f0.x, f0.y);
        __nv_bfloat162 p1 = __floats2bfloat162_rn(f0.z, f0.w);
        __nv_bfloat162 p2 = __floats2bfloat162_rn(f1.x, f1.y);
        __nv_bfloat162 p3 = __floats2bfloat162_rn(f1.z, f1.w);
        uint4 u;
        u.x = *(uint32_t*)&p0; u.y = *(uint32_t*)&p1;
        u.z = *(uint32_t*)&p2; u.w = *(uint32_t*)&p3;
        int i = (p << 8) + tid;
        int r = i >> 5;
        int cc = (i & 31) + 32;
        *(uint4*)(sm + A_OFF + SWZ16(r, cc)) = u;
    };

    // ---- Prologue: A k-half-0 (cols 0-255) + dsp reduce + v + prefetch 0-3 ----
    {
#pragma unroll 8
        for (int i = tid; i < 4096; i += 256) {
            int r = i >> 5;
            int c = i & 31;                       // 16B chunks 0..31 (bf16 cols 0..255)
            float4 f0 = srcA[(r << 7) + (c << 1)];
            float4 f1 = srcA[(r << 7) + (c << 1) + 1];
            __nv_bfloat162 p0 = __floats2bfloat162_rn(f0.x, f0.y);
            __nv_bfloat162 p1 = __floats2bfloat162_rn(f0.z, f0.w);
            __nv_bfloat162 p2 = __floats2bfloat162_rn(f1.x, f1.y);
            __nv_bfloat162 p3 = __floats2bfloat162_rn(f1.z, f1.w);
            uint4 u;
            u.x = *(uint32_t*)&p0; u.y = *(uint32_t*)&p1;
            u.z = *(uint32_t*)&p2; u.w = *(uint32_t*)&p3;
            *(uint4*)(sm + A_OFF + SWZ16(r, c)) = u;
        }
        for (int i = tid; i < MM; i += 256) {
            float s = bwd[i] + bud[i];
#pragma unroll
            for (int ks = 0; ks < 16; ks++)
                s += g_part[(ks * BB + b) * MM + i];
            dsp_s[i] = s;
            v_s[i] = vd[i];
        }
        // Prefetch first 4 half-1 pieces (in flight across the barrier)
        ldgPiece(0); ldgPiece(1); ldgPiece(2); ldgPiece(3);
    }

    float lp[4] = {0.f, 0.f, 0.f, 0.f};

    int aRow0 = (wm << 5) + (lane & 15);
    int aRow1 = aRow0 + 16;
    int aCadd = (lane >> 4);
    int bQuad = lane >> 3;
    int bRowIn = lane & 7;
    int bCadd = bQuad & 1;
    int bBlkHalf = bQuad >> 1;
    int bN0 = (wn << 5) + (bBlkHalf << 3) + bRowIn;
    int bN1 = bN0 + 16;

    uint32_t af[2][2][4];
    uint32_t bfr[2][2][4];

    auto loadFrags = [&](int buf, int ks) {
#pragma unroll
        for (int mi = 0; mi < 2; mi++) {
            int r = mi ? aRow1 : aRow0;
            uint32_t addr = sA + SWZ16(r, (ks << 1) + aCadd);
            asm volatile("ldmatrix.sync.aligned.m8n8.x4.shared.b16 {%0,%1,%2,%3}, [%4];"
                         : "=r"(af[buf][mi][0]), "=r"(af[buf][mi][1]),
                           "=r"(af[buf][mi][2]), "=r"(af[buf][mi][3]) : "r"(addr));
        }
#pragma unroll
        for (int jp = 0; jp < 2; jp++) {
            int n = jp ? bN1 : bN0;
            uint32_t addr = sB + SWZ16(n, (ks << 1) + bCadd);
            asm volatile("ldmatrix.sync.aligned.m8n8.x4.shared.b16 {%0,%1,%2,%3}, [%4];"
                         : "=r"(bfr[buf][jp][0]), "=r"(bfr[buf][jp][1]),
                           "=r"(bfr[buf][jp][2]), "=r"(bfr[buf][jp][3]) : "r"(addr));
        }
    };

    float acc[2][4][4];

    auto mmaStep = [&](int cur) {
#pragma unroll
        for (int mi = 0; mi < 2; mi++)
#pragma unroll
            for (int jp = 0; jp < 2; jp++) {
                asm volatile("mma.sync.aligned.m16n8k16.row.col.f32.bf16.bf16.f32 "
                    "{%0,%1,%2,%3}, {%4,%5,%6,%7}, {%8,%9}, {%0,%1,%2,%3};"
                    : "+f"(acc[mi][jp * 2][0]), "+f"(acc[mi][jp * 2][1]),
                      "+f"(acc[mi][jp * 2][2]), "+f"(acc[mi][jp * 2][3])
                    : "r"(af[cur][mi][0]), "r"(af[cur][mi][1]),
                      "r"(af[cur][mi][2]), "r"(af[cur][mi][3]),
                      "r"(bfr[cur][jp][0]), "r"(bfr[cur][jp][1]));
                asm volatile("mma.sync.aligned.m16n8k16.row.col.f32.bf16.bf16.f32 "
                    "{%0,%1,%2,%3}, {%4,%5,%6,%7}, {%8,%9}, {%0,%1,%2,%3};"
                    : "+f"(acc[mi][jp * 2 + 1][0]), "+f"(acc[mi][jp * 2 + 1][1]),
                      "+f"(acc[mi][jp * 2 + 1][2]), "+f"(acc[mi][jp * 2 + 1][3])
                    : "r"(af[cur][mi][0]), "r"(af[cur][mi][1]),
                      "r"(af[cur][mi][2]), "r"(af[cur][mi][3]),
                      "r"(bfr[cur][jp][2]), "r"(bfr[cur][jp][3]));
            }
    };

    for (int nc = 0; nc < 8; nc++) {
#pragma unroll
        for (int mi = 0; mi < 2; mi++)
#pragma unroll
            for (int j = 0; j < 4; j++)
#pragma unroll
                for (int q = 0; q < 4; q++) acc[mi][j][q] = 0.f;

#pragma unroll
        for (int h = 0; h < 2; h++) {
            cp_wait1();
            __syncthreads();
            int kbase = h << 4;

            loadFrags(0, kbase);
            if (h == 0 && nc == 0) {
                // Special phase: A half-1 streamed with strict depth-4 pipe.
                // stsPiece(kk) reads pf[kk&3]; ldgPiece(kk+4) then refills it.
#pragma unroll
                for (int kk = 0; kk < 16; kk++) {
                    int cur = kk & 1;
                    if (kk < 15) loadFrags(cur ^ 1, kk + 1);
                    stsPiece(kk);
                    if (kk < 12) ldgPiece(kk + 4);
                    mmaStep(cur);
                }
            } else {
#pragma unroll
                for (int kk = 0; kk < 16; kk++) {
                    int cur = kk & 1;
                    if (kk < 15) loadFrags(cur ^ 1, kbase + kk + 1);
                    mmaStep(cur);
                }
            }
            __syncthreads();
            if (nc < 7) loadBhalf(nc + 1, h);
            cp_commit();
        }

        int nbase = (nc << 6) + (wn << 5) + (tig << 1);
#pragma unroll
        for (int mi = 0; mi < 2; mi++)
#pragma unroll
            for (int j = 0; j < 4; j++) {
                int cb = nbase + (j << 3);
                float v0 = v_s[cb], v1 = v_s[cb + 1];
                float d0 = dsp_s[cb], d1 = dsp_s[cb + 1];
                lp[mi * 2 + 0] += v0 * tanh_fast(acc[mi][j][0] + d0)
                                + v1 * tanh_fast(acc[mi][j][1] + d1);
                lp[mi * 2 + 1] += v0 * tanh_fast(acc[mi][j][2] + d0)
                                + v1 * tanh_fast(acc[mi][j][3] + d1);
            }
    }

#pragma unroll
    for (int q = 0; q < 4; q++) {
        lp[q] += __shfl_xor_sync(0xffffffffu, lp[q], 1);
        lp[q] += __shfl_xor_sync(0xffffffffu, lp[q], 2);
    }
    int row[4];
    row[0] = (wm << 5) + g;
    row[1] = (wm << 5) + 8 + g;
    row[2] = (wm << 5) + 16 + g;
    row[3] = (wm << 5) + 24 + g;
    if (wn == 1 && tig == 0) {
#pragma unroll
        for (int q = 0; q < 4; q++) part[row[q]] = lp[q];
    }
    __syncthreads();
    if (wn == 0 && tig == 0) {
#pragma unroll
        for (int q = 0; q < 4; q++)
            g_l[b * TT + t0 + row[q]] = lp[q] + part[row[q]];
    }
}

// ---------------------------------------------------------------------------
// Kernel 3: softmax over T per batch. 1024 threads, 2 elements each.
// ---------------------------------------------------------------------------
__global__ __launch_bounds__(1024) void k_softmax(float* __restrict__ out) {
    __shared__ float redm[32];
    __shared__ float reds[32];
    int b = blockIdx.x, tid = threadIdx.x, lane = tid & 31, wid = tid >> 5;
    float v0 = g_l[b * TT + tid];
    float v1 = g_l[b * TT + 1024 + tid];
    float m = fmaxf(v0, v1);
#pragma unroll
    for (int o = 16; o; o >>= 1) m = fmaxf(m, __shfl_xor_sync(0xffffffffu, m, o));
    if (lane == 0) redm[wid] = m;
    __syncthreads();
    if (wid == 0) {
        float mm = redm[lane];
#pragma unroll
        for (int o = 16; o; o >>= 1) mm = fmaxf(mm, __shfl_xor_sync(0xffffffffu, mm, o));
        if (lane == 0) redm[0] = mm;
    }
    __syncthreads();
    m = redm[0];
    float e0 = __expf(v0 - m);
    float e1 = __expf(v1 - m);
    float s = e0 + e1;
#pragma unroll
    for (int o = 16; o; o >>= 1) s += __shfl_xor_sync(0xffffffffu, s, o);
    if (lane == 0) reds[wid] = s;
    __syncthreads();
    if (wid == 0) {
        float ss = reds[lane];
#pragma unroll
        for (int o = 16; o; o >>= 1) ss += __shfl_xor_sync(0xffffffffu, ss, o);
        if (lane == 0) reds[0] = ss;
    }
    __syncthreads();
    float inv = 1.0f / reds[0];
    out[b * TT + tid] = e0 * inv;
    out[b * TT + 1024 + tid] = e1 * inv;
}

// ---------------------------------------------------------------------------
extern "C" void kernel_launch(void* const* d_in, const int* in_sizes, int n_in,
                              void* d_out, int out_size) {
    const float* h   = (const float*)d_in[0];
    const float* c   = (const float*)d_in[1];
    const float* enc = (const float*)d_in[2];
    const float* W   = (const float*)d_in[3];
    const float* bwd = (const float*)d_in[4];
    const float* U   = (const float*)d_in[5];
    const float* bud = (const float*)d_in[6];
    const float* vd  = (const float*)d_in[7];
    float* out = (float*)d_out;

    cudaFuncSetAttribute(k_main, cudaFuncAttributeMaxDynamicSharedMemorySize, SMEM_TOTAL);

    k_prep<<<320, 512>>>(h, c, W, U);
    k_main<<<(BB * TT) / 128, 256, SMEM_TOTAL>>>(enc, vd, bwd, bud);
    k_softmax<<<BB, 1024>>>(out);
}